// round 2
// baseline (speedup 1.0000x reference)
#include <cuda_runtime.h>
#include <math.h>

typedef unsigned long long u64;

#define T_TOK 4096
#define HDIM  1024
#define IDIM  2048
#define NEXP  8
#define SLOTS (2 * T_TOK)

// ---------------- scratch (device globals; no allocation) ----------------
__device__ float g_xr[(size_t)T_TOK * HDIM];     // router output [T,H]      16 MB
__device__ float g_hs[(size_t)T_TOK * IDIM];     // shared-expert h [T,I]    32 MB
__device__ float g_h[(size_t)SLOTS * IDIM];      // expert h per slot        64 MB
__device__ float g_eout[(size_t)SLOTS * HDIM];   // expert down out per slot 32 MB
__device__ int   g_tok_e[T_TOK * 2];
__device__ float g_tok_w[T_TOK * 2];
__device__ int   g_tok_slot[T_TOK * 2];
__device__ int   g_counts[NEXP];
__device__ int   g_offsets[NEXP];
__device__ int   g_cursor[NEXP];
__device__ int   g_list_tok[SLOTS];
__device__ float g_list_w[SLOTS];

// ---------------- f32x2 helpers (sm_103a packed fp32) ----------------
__device__ __forceinline__ u64 dup2(float x) {
    u64 r; asm("mov.b64 %0, {%1,%1};" : "=l"(r) : "f"(x)); return r;
}
__device__ __forceinline__ void fma2(u64 &d, u64 a, u64 b) {
    asm("fma.rn.f32x2 %0, %1, %2, %3;" : "=l"(d) : "l"(a), "l"(b), "l"(d));
}
__device__ __forceinline__ void unp2(u64 v, float &x, float &y) {
    asm("mov.b64 {%0,%1}, %2;" : "=f"(x), "=f"(y) : "l"(v));
}

// ---------------- init: zero expert counters ----------------
__global__ void k_init() {
    int i = threadIdx.x;
    if (i < NEXP) { g_counts[i] = 0; g_cursor[i] = 0; }
}

// ---------------- router GEMM: xr = xf + tc @ tp_w + tp_b ----------------
// tiles 64x64, K-step 16, 256 threads, 4x4 per thread via f32x2
__global__ __launch_bounds__(256, 2) void k_router(
    const float* __restrict__ xf, const float* __restrict__ tc,
    const float* __restrict__ tpw, const float* __restrict__ tpb)
{
    __shared__ float As[16][68];
    __shared__ float Bs[16][64];
    const int tid = threadIdx.x;
    const int tx = tid & 15, ty = tid >> 4;
    const int m0 = blockIdx.y * 64, n0 = blockIdx.x * 64;
    const int lr = tid >> 2, lk = (tid & 3) << 2;   // A loader: row, k-chunk
    const int bk = tid >> 4, bn = (tid & 15) << 2;  // B loader: k, n-chunk

    const float* aptr = tc + (size_t)(m0 + lr) * HDIM + lk;
    const float* bptr = tpw + (size_t)bk * HDIM + n0 + bn;

    u64 acc[4][2];
#pragma unroll
    for (int i = 0; i < 4; i++) { acc[i][0] = 0ull; acc[i][1] = 0ull; }

    for (int k0 = 0; k0 < HDIM; k0 += 16) {
        float4 av = *(const float4*)(aptr + k0);
        float4 bv = *(const float4*)(bptr + (size_t)k0 * HDIM);
        As[lk + 0][lr] = av.x; As[lk + 1][lr] = av.y;
        As[lk + 2][lr] = av.z; As[lk + 3][lr] = av.w;
        *(float4*)&Bs[bk][bn] = bv;
        __syncthreads();
#pragma unroll
        for (int kk = 0; kk < 16; kk++) {
            const float4 a = *(const float4*)&As[kk][ty << 2];
            const ulonglong2 b = *(const ulonglong2*)&Bs[kk][tx << 2];
            u64 a2[4] = { dup2(a.x), dup2(a.y), dup2(a.z), dup2(a.w) };
#pragma unroll
            for (int i = 0; i < 4; i++) { fma2(acc[i][0], a2[i], b.x); fma2(acc[i][1], a2[i], b.y); }
        }
        __syncthreads();
    }

    const float4 bias = *(const float4*)(tpb + n0 + (tx << 2));
#pragma unroll
    for (int i = 0; i < 4; i++) {
        int row = m0 + (ty << 2) + i;
        float4 xv = *(const float4*)(xf + (size_t)row * HDIM + n0 + (tx << 2));
        float c0, c1, c2, c3;
        unp2(acc[i][0], c0, c1); unp2(acc[i][1], c2, c3);
        float4 o;
        o.x = c0 + xv.x + bias.x; o.y = c1 + xv.y + bias.y;
        o.z = c2 + xv.z + bias.z; o.w = c3 + xv.w + bias.w;
        *(float4*)(g_xr + (size_t)row * HDIM + n0 + (tx << 2)) = o;
    }
}

// ---------------- gate: logits, softmax, top-2, histogram ----------------
// one warp per token
__global__ void k_gate(const float* __restrict__ gw) {
    int t = (blockIdx.x * blockDim.x + threadIdx.x) >> 5;
    int lane = threadIdx.x & 31;
    if (t >= T_TOK) return;
    const float* xr = g_xr + (size_t)t * HDIM;
    float acc[8] = {0.f, 0.f, 0.f, 0.f, 0.f, 0.f, 0.f, 0.f};
    for (int h = lane; h < HDIM; h += 32) {
        float xv = xr[h];
        float4 w0 = *(const float4*)(gw + (size_t)h * 8);
        float4 w1 = *(const float4*)(gw + (size_t)h * 8 + 4);
        acc[0] += xv * w0.x; acc[1] += xv * w0.y; acc[2] += xv * w0.z; acc[3] += xv * w0.w;
        acc[4] += xv * w1.x; acc[5] += xv * w1.y; acc[6] += xv * w1.z; acc[7] += xv * w1.w;
    }
#pragma unroll
    for (int o = 16; o; o >>= 1)
#pragma unroll
        for (int e = 0; e < 8; e++)
            acc[e] += __shfl_down_sync(0xffffffffu, acc[e], o);
    if (lane == 0) {
        float mx = acc[0];
#pragma unroll
        for (int e = 1; e < 8; e++) mx = fmaxf(mx, acc[e]);
        float p[8]; float Z = 0.f;
#pragma unroll
        for (int e = 0; e < 8; e++) { p[e] = __expf(acc[e] - mx); Z += p[e]; }
        float rZ = 1.f / Z;
#pragma unroll
        for (int e = 0; e < 8; e++) p[e] *= rZ;
        int i0 = 0; float p0 = p[0];
#pragma unroll
        for (int e = 1; e < 8; e++) if (p[e] > p0) { p0 = p[e]; i0 = e; }
        int i1 = -1; float p1 = -1.f;
#pragma unroll
        for (int e = 0; e < 8; e++) if (e != i0 && p[e] > p1) { p1 = p[e]; i1 = e; }
        float s = 1.f / (p0 + p1 + 1e-5f);
        g_tok_e[2 * t] = i0;     g_tok_w[2 * t] = p0 * s;
        g_tok_e[2 * t + 1] = i1; g_tok_w[2 * t + 1] = p1 * s;
        atomicAdd(&g_counts[i0], 1); atomicAdd(&g_counts[i1], 1);
    }
}

// ---------------- offsets: exclusive scan over E=8 ----------------
__global__ void k_offsets() {
    if (threadIdx.x == 0) {
        int s = 0;
        for (int e = 0; e < NEXP; e++) { g_offsets[e] = s; s += g_counts[e]; g_cursor[e] = 0; }
    }
}

// ---------------- placement: fill per-expert token segments ----------------
__global__ void k_place() {
    int t = blockIdx.x * blockDim.x + threadIdx.x;
    if (t >= T_TOK) return;
#pragma unroll
    for (int k = 0; k < 2; k++) {
        int e = g_tok_e[2 * t + k];
        int pos = g_offsets[e] + atomicAdd(&g_cursor[e], 1);
        g_list_tok[pos] = t;
        g_list_w[pos] = g_tok_w[2 * t + k];
        g_tok_slot[2 * t + k] = pos;
    }
}

// ---------------- fused gate+up+silu: h = w * silu(X@Wg) * (X@Wu) ----------------
// expert_mode=1: gathered segment per blockIdx.z, weights eg/eu, out g_h
// expert_mode=0: dense (shared expert), weights sg/su, out g_hs
__global__ __launch_bounds__(256, 2) void k_gateup(
    const float* __restrict__ X,
    const float* __restrict__ Wg, const float* __restrict__ Wu,
    int expert_mode)
{
    const int e = blockIdx.z;
    int cnt, off;
    const float *wg, *wu;
    float* Hout;
    if (expert_mode) {
        cnt = g_counts[e]; off = g_offsets[e];
        wg = Wg + (size_t)e * HDIM * IDIM; wu = Wu + (size_t)e * HDIM * IDIM;
        Hout = g_h;
    } else {
        cnt = T_TOK; off = 0; wg = Wg; wu = Wu; Hout = g_hs;
    }
    const int m0 = blockIdx.y * 64;
    if (m0 >= cnt) return;

    __shared__ float As[16][68];
    __shared__ float Bg[16][64];
    __shared__ float Bu[16][64];
    const int tid = threadIdx.x;
    const int tx = tid & 15, ty = tid >> 4;
    const int n0 = blockIdx.x * 64;
    const int lr = tid >> 2, lk = (tid & 3) << 2;
    const int bk = tid >> 4, bn = (tid & 15) << 2;

    const int arow = m0 + lr;
    const bool avalid = arow < cnt;
    const int atok = avalid ? (expert_mode ? g_list_tok[off + arow] : arow) : 0;
    const float* aptr = X + (size_t)atok * HDIM + lk;
    const float* gptr = wg + (size_t)bk * IDIM + n0 + bn;
    const float* uptr = wu + (size_t)bk * IDIM + n0 + bn;

    u64 ag[4][2], au[4][2];
#pragma unroll
    for (int i = 0; i < 4; i++) { ag[i][0] = ag[i][1] = 0ull; au[i][0] = au[i][1] = 0ull; }

    for (int k0 = 0; k0 < HDIM; k0 += 16) {
        float4 av = avalid ? *(const float4*)(aptr + k0) : make_float4(0.f, 0.f, 0.f, 0.f);
        float4 gv = *(const float4*)(gptr + (size_t)k0 * IDIM);
        float4 uv = *(const float4*)(uptr + (size_t)k0 * IDIM);
        As[lk + 0][lr] = av.x; As[lk + 1][lr] = av.y;
        As[lk + 2][lr] = av.z; As[lk + 3][lr] = av.w;
        *(float4*)&Bg[bk][bn] = gv;
        *(float4*)&Bu[bk][bn] = uv;
        __syncthreads();
#pragma unroll
        for (int kk = 0; kk < 16; kk++) {
            const float4 a = *(const float4*)&As[kk][ty << 2];
            const ulonglong2 bgp = *(const ulonglong2*)&Bg[kk][tx << 2];
            const ulonglong2 bup = *(const ulonglong2*)&Bu[kk][tx << 2];
            u64 a2[4] = { dup2(a.x), dup2(a.y), dup2(a.z), dup2(a.w) };
#pragma unroll
            for (int i = 0; i < 4; i++) {
                fma2(ag[i][0], a2[i], bgp.x); fma2(ag[i][1], a2[i], bgp.y);
                fma2(au[i][0], a2[i], bup.x); fma2(au[i][1], a2[i], bup.y);
            }
        }
        __syncthreads();
    }

#pragma unroll
    for (int i = 0; i < 4; i++) {
        int row = m0 + (ty << 2) + i;
        if (row < cnt) {
            float w = expert_mode ? g_list_w[off + row] : 1.0f;
            float gvv[4], uvv[4];
            unp2(ag[i][0], gvv[0], gvv[1]); unp2(ag[i][1], gvv[2], gvv[3]);
            unp2(au[i][0], uvv[0], uvv[1]); unp2(au[i][1], uvv[2], uvv[3]);
            float4 o;
            float* op = (float*)&o;
#pragma unroll
            for (int j = 0; j < 4; j++) {
                float g = gvv[j];
                float sig = 1.f / (1.f + __expf(-g));
                op[j] = w * (g * sig) * uvv[j];
            }
            *(float4*)(Hout + (size_t)(off + row) * IDIM + n0 + (tx << 2)) = o;
        }
    }
}

// ---------------- down projection ----------------
// expert_mode=1: g_h segment @ ed[e] -> g_eout (per slot)
// expert_mode=0: g_hs @ sd -> out (direct write; first writer)
__global__ __launch_bounds__(256, 2) void k_down(
    const float* __restrict__ Wd, float* __restrict__ out, int expert_mode)
{
    const int e = blockIdx.z;
    int cnt, off;
    const float* wd;
    const float* Hin;
    if (expert_mode) {
        cnt = g_counts[e]; off = g_offsets[e];
        wd = Wd + (size_t)e * IDIM * HDIM; Hin = g_h;
    } else {
        cnt = T_TOK; off = 0; wd = Wd; Hin = g_hs;
    }
    const int m0 = blockIdx.y * 64;
    if (m0 >= cnt) return;

    __shared__ float As[16][68];
    __shared__ float Bs[16][64];
    const int tid = threadIdx.x;
    const int tx = tid & 15, ty = tid >> 4;
    const int n0 = blockIdx.x * 64;
    const int lr = tid >> 2, lk = (tid & 3) << 2;
    const int bk = tid >> 4, bn = (tid & 15) << 2;

    const int arow = m0 + lr;
    const bool avalid = arow < cnt;
    const float* aptr = Hin + (size_t)(off + (avalid ? arow : 0)) * IDIM + lk;
    const float* bptr = wd + (size_t)bk * HDIM + n0 + bn;

    u64 acc[4][2];
#pragma unroll
    for (int i = 0; i < 4; i++) { acc[i][0] = 0ull; acc[i][1] = 0ull; }

    for (int k0 = 0; k0 < IDIM; k0 += 16) {
        float4 av = avalid ? *(const float4*)(aptr + k0) : make_float4(0.f, 0.f, 0.f, 0.f);
        float4 bv = *(const float4*)(bptr + (size_t)k0 * HDIM);
        As[lk + 0][lr] = av.x; As[lk + 1][lr] = av.y;
        As[lk + 2][lr] = av.z; As[lk + 3][lr] = av.w;
        *(float4*)&Bs[bk][bn] = bv;
        __syncthreads();
#pragma unroll
        for (int kk = 0; kk < 16; kk++) {
            const float4 a = *(const float4*)&As[kk][ty << 2];
            const ulonglong2 b = *(const ulonglong2*)&Bs[kk][tx << 2];
            u64 a2[4] = { dup2(a.x), dup2(a.y), dup2(a.z), dup2(a.w) };
#pragma unroll
            for (int i = 0; i < 4; i++) { fma2(acc[i][0], a2[i], b.x); fma2(acc[i][1], a2[i], b.y); }
        }
        __syncthreads();
    }

#pragma unroll
    for (int i = 0; i < 4; i++) {
        int row = m0 + (ty << 2) + i;
        if (row < cnt) {
            float c0, c1, c2, c3;
            unp2(acc[i][0], c0, c1); unp2(acc[i][1], c2, c3);
            float4 o; o.x = c0; o.y = c1; o.z = c2; o.w = c3;
            if (expert_mode) {
                *(float4*)(g_eout + (size_t)(off + row) * HDIM + n0 + (tx << 2)) = o;
            } else {
                *(float4*)(out + (size_t)row * HDIM + n0 + (tx << 2)) = o;
            }
        }
    }
}

// ---------------- deterministic combine: out += eout[slot0] + eout[slot1] ----------------
__global__ void k_combine(float* __restrict__ out) {
    int gid = blockIdx.x * blockDim.x + threadIdx.x;  // over T*H/4 float4s
    int t = gid / (HDIM / 4);
    int c = (gid % (HDIM / 4)) * 4;
    if (t >= T_TOK) return;
    int s0 = g_tok_slot[2 * t], s1 = g_tok_slot[2 * t + 1];
    float4 o = *(const float4*)(out + (size_t)t * HDIM + c);
    float4 a = *(const float4*)(g_eout + (size_t)s0 * HDIM + c);
    float4 b = *(const float4*)(g_eout + (size_t)s1 * HDIM + c);
    o.x += a.x + b.x; o.y += a.y + b.y; o.z += a.z + b.z; o.w += a.w + b.w;
    *(float4*)(out + (size_t)t * HDIM + c) = o;
}

// ---------------- launch ----------------
extern "C" void kernel_launch(void* const* d_in, const int* in_sizes, int n_in,
                              void* d_out, int out_size) {
    const float* x   = (const float*)d_in[0];
    const float* tcx = (const float*)d_in[1];
    const float* tpw = (const float*)d_in[2];
    const float* tpb = (const float*)d_in[3];
    const float* gw  = (const float*)d_in[4];
    const float* eg  = (const float*)d_in[5];
    const float* eu  = (const float*)d_in[6];
    const float* ed  = (const float*)d_in[7];
    const float* sg  = (const float*)d_in[8];
    const float* su  = (const float*)d_in[9];
    const float* sd  = (const float*)d_in[10];
    float* out = (float*)d_out;

    dim3 thr(256);

    k_init<<<1, 32>>>();
    k_router<<<dim3(HDIM / 64, T_TOK / 64), thr>>>(x, tcx, tpw, tpb);
    k_gate<<<T_TOK / 8, 256>>>(gw);
    k_offsets<<<1, 32>>>();
    k_place<<<T_TOK / 256, 256>>>();
    // shared expert gate/up (dense)
    k_gateup<<<dim3(IDIM / 64, T_TOK / 64), thr>>>(x, sg, su, 0);
    // sparse experts gate/up
    k_gateup<<<dim3(IDIM / 64, T_TOK / 64, NEXP), thr>>>(x, eg, eu, 1);
    // shared expert down -> writes out
    k_down<<<dim3(HDIM / 64, T_TOK / 64), thr>>>(sd, out, 0);
    // expert down -> per-slot scratch
    k_down<<<dim3(HDIM / 64, T_TOK / 64, NEXP), thr>>>(ed, out, 1);
    // deterministic combine
    k_combine<<<(T_TOK * (HDIM / 4)) / 256, 256>>>(out);
}